// round 14
// baseline (speedup 1.0000x reference)
#include <cuda_runtime.h>
#include <cuda_fp16.h>
#include <cstdint>
#include <math.h>

// MusicRNN: 2-layer LSTM (B=2048, T=256, I=88, H=64) + FC (O=13).
// R13: recurrence restructured for IN-REGISTER activation:
//  - warp w owns gate rows j = quad*64 + 4w + (0..3) for all 4 quads (i,f,g,o)
//    -> after MMA, one shfl_xor(16) lane-pair exchange yields all 4 gates of
//    each cell in registers. No gate SMEM round-trip, no BAR1.
//  - h buffers double-buffered -> ONE __syncthreads per step (was two).
// Structure: gemm1 -> fused 2-layer rec (+FC head). Math identical to R12.

namespace {
constexpr int B = 2048, T = 256, I = 88, H = 64, O = 13, G4 = 256;
constexpr int NTILES = T * (B / 128);       // 4096 tiles of 128 rows
constexpr int HBS = 24;                      // hB row stride (words)
}

// scratch (static __device__: allocation-free rule)
__device__ __half g_pre1[(size_t)T * B * G4];   // 256 MB: x @ W_ih0^T + bias0

// ---------------- warp-MMA fp16 (baseline PTX, works on .target sm_103) ----
__device__ __forceinline__ void mma16816(float* c, const uint32_t* a,
                                         uint32_t b0, uint32_t b1) {
    asm volatile(
        "mma.sync.aligned.m16n8k16.row.col.f32.f16.f16.f32 "
        "{%0,%1,%2,%3}, {%4,%5,%6,%7}, {%8,%9}, {%0,%1,%2,%3};"
        : "+f"(c[0]), "+f"(c[1]), "+f"(c[2]), "+f"(c[3])
        : "r"(a[0]), "r"(a[1]), "r"(a[2]), "r"(a[3]), "r"(b0), "r"(b1));
}
__device__ __forceinline__ uint32_t ld32h(const __half* p) {
    return *(const uint32_t*)p;
}
__device__ __forceinline__ void split_f16(float v, __half& h, __half& l) {
    h = __float2half_rn(v);
    l = __float2half_rn(v - __half2float(h));
}
__device__ __forceinline__ uint32_t packh(__half a, __half b) {
    return (uint32_t)__half_as_ushort(a) | ((uint32_t)__half_as_ushort(b) << 16);
}
__device__ __forceinline__ uint32_t packf(float a, float b) {
    return packh(__float2half_rn(a), __float2half_rn(b));
}
__device__ __forceinline__ float ftanh(float x) {
    float y; asm("tanh.approx.f32 %0, %1;" : "=f"(y) : "f"(x)); return y;
}
__device__ __forceinline__ float fsig(float x) {
    float y; asm("tanh.approx.f32 %0, %1;" : "=f"(y) : "f"(0.5f * x));
    return fmaf(0.5f, y, 0.5f);
}

// ---------------- pre-GEMM 1 (unchanged from passing R12) ------------------
template <int KDATA, int KP>
__global__ void __launch_bounds__(512, 1) gemm_pre_mma(
    const float* __restrict__ src,   // x [B][T][KDATA]
    const float* __restrict__ w,     // [256][KDATA]
    const float* __restrict__ bia, const float* __restrict__ bib)
{
    constexpr int SA = KP + 8;
    extern __shared__ __half smh[];
    __half* sWH = smh;
    __half* sWL = sWH + 256 * SA;
    __half* sA  = sWL + 256 * SA;

    const int tid = threadIdx.x;
    for (int i = tid; i < 640 * SA / 2; i += 512)
        ((uint32_t*)smh)[i] = 0u;
    __syncthreads();

    for (int idx = tid; idx < 256 * KDATA; idx += 512) {
        int j = idx / KDATA, k = idx - j * KDATA;
        __half h, l;
        split_f16(w[idx], h, l);
        sWH[j * SA + k] = h;
        sWL[j * SA + k] = l;
    }
    if (tid < 256) {
        __half h, l;
        split_f16(bia[tid] + bib[tid], h, l);
        sWH[tid * SA + KDATA] = h;
        sWL[tid * SA + KDATA] = l;
    }
    if (tid < 128)
        sA[tid * SA + KDATA] = __float2half_rn(1.0f);

    const int lane = tid & 31, wid = tid >> 5;
    const int g = lane >> 2, tg = lane & 3;
    const int wRow = (wid & 3) * 32;
    const int wCol = (wid >> 2) * 64;

    for (int tile = blockIdx.x; tile < NTILES; tile += gridDim.x) {
        const int t = tile >> 4, b0 = (tile & 15) << 7;

        __syncthreads();
        for (int idx = tid; idx < 128 * (KDATA / 2); idx += 512) {
            int m = idx / (KDATA / 2), kp = idx - m * (KDATA / 2);
            const float* rp = src + ((size_t)(b0 + m) * T + t) * KDATA;
            float2 v = *(const float2*)(rp + 2 * kp);
            __half2 hp;
            hp.x = __float2half_rn(v.x);
            hp.y = __float2half_rn(v.y);
            *(__half2*)(sA + m * SA + 2 * kp) = hp;
        }
        __syncthreads();

        float acc[2][8][4] = {};
        #pragma unroll
        for (int kk = 0; kk < KP / 16; ++kk) {
            uint32_t ah[2][4];
            #pragma unroll
            for (int f = 0; f < 2; ++f) {
                const int base = (wRow + f * 16 + g) * SA + kk * 16 + tg * 2;
                ah[f][0] = ld32h(sA + base);
                ah[f][1] = ld32h(sA + base + 8 * SA);
                ah[f][2] = ld32h(sA + base + 8);
                ah[f][3] = ld32h(sA + base + 8 * SA + 8);
            }
            #pragma unroll
            for (int n = 0; n < 8; ++n) {
                const int bbase = (wCol + n * 8 + g) * SA + kk * 16 + tg * 2;
                const uint32_t bh0 = ld32h(sWH + bbase);
                const uint32_t bh1 = ld32h(sWH + bbase + 8);
                const uint32_t bl0 = ld32h(sWL + bbase);
                const uint32_t bl1 = ld32h(sWL + bbase + 8);
                #pragma unroll
                for (int f = 0; f < 2; ++f) {
                    mma16816(acc[f][n], ah[f], bh0, bh1);
                    mma16816(acc[f][n], ah[f], bl0, bl1);
                }
            }
        }

        __half* orow = g_pre1 + ((size_t)t * B + b0) * G4;
        #pragma unroll
        for (int f = 0; f < 2; ++f) {
            const int r0 = wRow + f * 16 + g;
            #pragma unroll
            for (int n = 0; n < 8; ++n) {
                const int col = wCol + n * 8 + tg * 2;
                __stcs((uint32_t*)(orow + (size_t)r0 * G4 + col),
                       packf(acc[f][n][0], acc[f][n][1]));
                __stcs((uint32_t*)(orow + (size_t)(r0 + 8) * G4 + col),
                       packf(acc[f][n][2], acc[f][n][3]));
            }
        }
    }
}

// ---------------- fused 2-layer recurrence: in-register activation ---------
// Warp w owns j = quad*64 + 4w + (0..3) for quad=0..3 (all four gates of
// h in [4w, 4w+4)). Cell of lane (g,tg): h = 4w + (g&3), b = 8nt + 2tg + s
// where s = g>=4. One shfl_xor(16) pairs lanes (g, g^4) to assemble all 4
// gates in registers. Single barrier per step (double-buffered h).
__global__ void __launch_bounds__(512, 1) lstm_fused(
    const float* __restrict__ w_hh0,  // [256][64]
    const float* __restrict__ w_ih1,  // [256][64]
    const float* __restrict__ w_hh1,  // [256][64]
    const float* __restrict__ bi1,    // [256]
    const float* __restrict__ bh1,    // [256]
    const float* __restrict__ fc_w,   // [O][H]
    const float* __restrict__ fc_b,   // [O]
    float* __restrict__ out)          // [B][O]
{
    extern __shared__ uint32_t smu[];
    uint32_t* hB1buf = smu;                    // [2][32][HBS] h1 (double buf)
    uint32_t* hB2buf = smu + 1536;             // [2][32][HBS] h2 (double buf)
    uint32_t* sWD    = smu + 3072;             // [16 words][512] W_hh1 frags
    float* sHL       = (float*)(smu + 3072 + 8192);  // [64][20]

    const int tid = threadIdx.x;
    const int lane = tid & 31, w = tid >> 5;
    const int g = lane >> 2, tg = lane & 3;
    const int s = g >> 2;                      // 0 for g<4, 1 for g>=4
    const int batch0 = blockIdx.x * 16;

    for (int i = tid; i < 3072; i += 512) smu[i] = 0u;   // both h bufs = 0

    // static A frags with GATE-INTERLEAVED row mapping:
    // logical r16 = g + (r&1)*8; j = (r16>>2)*64 + 4w + (r16&3)
    uint32_t a_h[4][4], a_l[4][4], c_h[4][4], c_l[4][4];
    #pragma unroll
    for (int kk = 0; kk < 4; ++kk) {
        #pragma unroll
        for (int r = 0; r < 4; ++r) {
            const int r16 = g + (r & 1) * 8;
            const int j = (r16 >> 2) * 64 + 4 * w + (r16 & 3);
            const int col = 16 * kk + 2 * tg + (r >> 1) * 8;
            __half h0, l0, h1, l1;
            float2 v = *(const float2*)(w_hh0 + j * 64 + col);
            split_f16(v.x, h0, l0); split_f16(v.y, h1, l1);
            a_h[kk][r] = packh(h0, h1); a_l[kk][r] = packh(l0, l1);
            float2 u = *(const float2*)(w_ih1 + j * 64 + col);
            split_f16(u.x, h0, l0); split_f16(u.y, h1, l1);
            c_h[kk][r] = packh(h0, h1); c_l[kk][r] = packh(l0, l1);
            float2 z = *(const float2*)(w_hh1 + j * 64 + col);
            sWD[(kk * 4 + r) * 512 + tid] =
                packh(__float2half_rn(z.x), __float2half_rn(z.y));
        }
    }

    // this lane's cells: h fixed, b = 8*nt + 2*tg + s for nt = 0,1
    const int h = 4 * w + (g & 3);
    const int bA = 2 * tg + s;        // nt = 0
    const int bBt = 8 + bA;           // nt = 1
    float c1_reg[2] = {0.f, 0.f};
    float c2_reg[2] = {0.f, 0.f};
    float bv[4];
    #pragma unroll
    for (int p = 0; p < 4; ++p)
        bv[p] = bi1[p * 64 + h] + bh1[p * 64 + h];
    __syncthreads();

    for (int t = 0; t < T; ++t) {
        const uint32_t* hb1r = hB1buf + (t & 1) * 768;
        uint32_t* hb1w       = hB1buf + ((t + 1) & 1) * 768;
        const uint32_t* hb2r = hB2buf + (t & 1) * 768;
        uint32_t* hb2w       = hB2buf + ((t + 1) & 1) * 768;

        // prefetch pre1[t] fp16 for this lane's cells (overlaps MMA)
        const __half* pt = g_pre1 + ((size_t)t * B + batch0) * G4;
        float pv[2][4];
        #pragma unroll
        for (int nt = 0; nt < 2; ++nt) {
            const int b = nt ? bBt : bA;
            #pragma unroll
            for (int p = 0; p < 4; ++p) {
                unsigned short us =
                    __ldcs((const unsigned short*)(pt + b * G4 + p * 64 + h));
                pv[nt][p] = __half2float(__ushort_as_half(us));
            }
        }

        float acc1[2][4] = {};
        float acc2[2][4] = {};
        // part 1: B = h1[t-1]
        #pragma unroll
        for (int kk = 0; kk < 4; ++kk) {
            #pragma unroll
            for (int nt = 0; nt < 2; ++nt) {
                const int c0 = (8 * kk + tg) * HBS + 8 * nt + g;
                const int c1 = (8 * kk + 4 + tg) * HBS + 8 * nt + g;
                const uint32_t b0 = hb1r[c0], b1 = hb1r[c1];
                mma16816(acc1[nt], a_h[kk], b0, b1);
                mma16816(acc2[nt], c_h[kk], b0, b1);
                mma16816(acc1[nt], a_l[kk], b0, b1);
                mma16816(acc2[nt], c_l[kk], b0, b1);
            }
        }
        // part 2: B = h2[t-2]
        #pragma unroll
        for (int kk = 0; kk < 4; ++kk) {
            uint32_t dh[4];
            #pragma unroll
            for (int r = 0; r < 4; ++r)
                dh[r] = sWD[(kk * 4 + r) * 512 + tid];
            #pragma unroll
            for (int nt = 0; nt < 2; ++nt) {
                const int c0 = (8 * kk + tg) * HBS + 8 * nt + g;
                const int c1 = (8 * kk + 4 + tg) * HBS + 8 * nt + g;
                mma16816(acc2[nt], dh, hb2r[c0], hb2r[c1]);
            }
        }

        // ---- in-register gate assembly + activation, layer 1
        #pragma unroll
        for (int nt = 0; nt < 2; ++nt) {
            const float ownA = s ? acc1[nt][1] : acc1[nt][0];
            const float ownB = s ? acc1[nt][3] : acc1[nt][2];
            const float rxA = __shfl_xor_sync(0xffffffffu,
                                s ? acc1[nt][0] : acc1[nt][1], 16);
            const float rxB = __shfl_xor_sync(0xffffffffu,
                                s ? acc1[nt][2] : acc1[nt][3], 16);
            float gi = (s ? rxA : ownA) + pv[nt][0];
            float gf = (s ? ownA : rxA) + pv[nt][1];
            float gg = (s ? rxB : ownB) + pv[nt][2];
            float go = (s ? ownB : rxB) + pv[nt][3];
            gi = fsig(gi); gf = fsig(gf); go = fsig(go); gg = ftanh(gg);
            const float c = gf * c1_reg[nt] + gi * gg;
            c1_reg[nt] = c;
            const float hv = go * ftanh(c);
            const int b = nt ? bBt : bA;
            ((unsigned short*)hb1w)[((h >> 1) * HBS + b) * 2 + (h & 1)] =
                __half_as_ushort(__float2half_rn(hv));
        }
        // ---- layer 2 (updates h2[t-1]; skip at t=0)
        if (t >= 1) {
            #pragma unroll
            for (int nt = 0; nt < 2; ++nt) {
                const float ownA = s ? acc2[nt][1] : acc2[nt][0];
                const float ownB = s ? acc2[nt][3] : acc2[nt][2];
                const float rxA = __shfl_xor_sync(0xffffffffu,
                                    s ? acc2[nt][0] : acc2[nt][1], 16);
                const float rxB = __shfl_xor_sync(0xffffffffu,
                                    s ? acc2[nt][2] : acc2[nt][3], 16);
                float gi = (s ? rxA : ownA) + bv[0];
                float gf = (s ? ownA : rxA) + bv[1];
                float gg = (s ? rxB : ownB) + bv[2];
                float go = (s ? ownB : rxB) + bv[3];
                gi = fsig(gi); gf = fsig(gf); go = fsig(go); gg = ftanh(gg);
                const float c = gf * c2_reg[nt] + gi * gg;
                c2_reg[nt] = c;
                const float hv = go * ftanh(c);
                const int b = nt ? bBt : bA;
                ((unsigned short*)hb2w)[((h >> 1) * HBS + b) * 2 + (h & 1)] =
                    __half_as_ushort(__float2half_rn(hv));
            }
        } else {
            // t=0: shfls must still execute uniformly? No: whole warp takes
            // the same branch (t uniform). Nothing to do.
        }
        __syncthreads();   // single barrier: h[t] visible for step t+1
    }

    // epilogue: gates2[T-1] from h1[T-1], h2[T-2] (both in buf[T&1]=buf0)
    {
        const uint32_t* hb1r = hB1buf + (T & 1) * 768;
        const uint32_t* hb2r = hB2buf + (T & 1) * 768;
        float acc2[2][4] = {};
        #pragma unroll
        for (int kk = 0; kk < 4; ++kk) {
            uint32_t dh[4];
            #pragma unroll
            for (int r = 0; r < 4; ++r)
                dh[r] = sWD[(kk * 4 + r) * 512 + tid];
            #pragma unroll
            for (int nt = 0; nt < 2; ++nt) {
                const int c0 = (8 * kk + tg) * HBS + 8 * nt + g;
                const int c1 = (8 * kk + 4 + tg) * HBS + 8 * nt + g;
                const uint32_t b0 = hb1r[c0], b1 = hb1r[c1];
                mma16816(acc2[nt], c_h[kk], b0, b1);
                mma16816(acc2[nt], c_l[kk], b0, b1);
                mma16816(acc2[nt], dh, hb2r[c0], hb2r[c1]);
            }
        }
        #pragma unroll
        for (int nt = 0; nt < 2; ++nt) {
            const float ownA = s ? acc2[nt][1] : acc2[nt][0];
            const float ownB = s ? acc2[nt][3] : acc2[nt][2];
            const float rxA = __shfl_xor_sync(0xffffffffu,
                                s ? acc2[nt][0] : acc2[nt][1], 16);
            const float rxB = __shfl_xor_sync(0xffffffffu,
                                s ? acc2[nt][2] : acc2[nt][3], 16);
            float gi = (s ? rxA : ownA) + bv[0];
            float gf = (s ? ownA : rxA) + bv[1];
            float gg = (s ? rxB : ownB) + bv[2];
            float go = (s ? ownB : rxB) + bv[3];
            gi = fsig(gi); gf = fsig(gf); go = fsig(go); gg = ftanh(gg);
            const float c = gf * c2_reg[nt] + gi * gg;
            const int b = nt ? bBt : bA;
            sHL[h * 20 + b] = go * ftanh(c);
        }
        __syncthreads();
    }

    // FC head: out = h2_last @ fc_w^T + fc_b
    for (int idx = tid; idx < 16 * O; idx += 512) {
        int b = idx / O, o = idx - (idx / O) * O;
        float sum = fc_b[o];
        #pragma unroll
        for (int hh = 0; hh < H; ++hh)
            sum += sHL[hh * 20 + b] * fc_w[o * H + hh];
        out[(batch0 + b) * O + o] = sum;
    }
}

extern "C" void kernel_launch(void* const* d_in, const int* in_sizes, int n_in,
                              void* d_out, int out_size) {
    const float* x     = (const float*)d_in[0];
    const float* w_ih0 = (const float*)d_in[1];
    const float* w_hh0 = (const float*)d_in[2];
    const float* b_ih0 = (const float*)d_in[3];
    const float* b_hh0 = (const float*)d_in[4];
    const float* w_ih1 = (const float*)d_in[5];
    const float* w_hh1 = (const float*)d_in[6];
    const float* b_ih1 = (const float*)d_in[7];
    const float* b_hh1 = (const float*)d_in[8];
    const float* fc_w  = (const float*)d_in[9];
    const float* fc_b  = (const float*)d_in[10];
    float* out = (float*)d_out;

    const int smG1 = 640 * (96 + 8) * 2;    // 133120 B
    const int smR = (3072 + 8192 + 64 * 20) * 4 + 256;   // ~50 KB

    cudaFuncSetAttribute(gemm_pre_mma<88, 96>,
                         cudaFuncAttributeMaxDynamicSharedMemorySize, smG1);
    cudaFuncSetAttribute(lstm_fused,
                         cudaFuncAttributeMaxDynamicSharedMemorySize, smR);

    gemm_pre_mma<88, 96><<<148, 512, smG1>>>(x, w_ih0, b_ih0, b_hh0);
    lstm_fused<<<B / 16, 512, smR>>>(
        w_hh0, w_ih1, w_hh1, b_ih1, b_hh1, fc_w, fc_b, out);
}

// round 15
// speedup vs baseline: 1.3376x; 1.3376x over previous
#include <cuda_runtime.h>
#include <cuda_fp16.h>
#include <cstdint>
#include <math.h>

// MusicRNN: 2-layer LSTM (B=2048, T=256, I=88, H=64) + FC (O=13).
// R14: ONE kernel. The x-projection (old gemm1) is fused into the rec
// kernel: x[t+1] staged per-step into SMEM (pair-packed B-frag layout,
// double-buffered -> no extra barrier), W_ih0 as single-fp16 per-thread
// frag cache, bias0 as activation constants. Deletes the gemm1 launch and
// all 512MB of g_pre traffic. Rec structure = R12 (best known: smem gate
// exchange, 2 barriers/step); R13's shfl experiment reverted.

namespace {
constexpr int B = 2048, T = 256, I = 88, H = 64, O = 13, G4 = 256;
constexpr int HBS = 24;                      // hB / xB row stride (words)
constexpr int GS2 = 13;                      // packed gate row stride (words)
constexpr int XP  = 44;                      // x pair-words per batch (88/2)
constexpr int XBUF = 48 * HBS;               // 1152 words per x buffer
}

// ---------------- helpers (baseline PTX only) ------------------------------
__device__ __forceinline__ void mma16816(float* c, const uint32_t* a,
                                         uint32_t b0, uint32_t b1) {
    asm volatile(
        "mma.sync.aligned.m16n8k16.row.col.f32.f16.f16.f32 "
        "{%0,%1,%2,%3}, {%4,%5,%6,%7}, {%8,%9}, {%0,%1,%2,%3};"
        : "+f"(c[0]), "+f"(c[1]), "+f"(c[2]), "+f"(c[3])
        : "r"(a[0]), "r"(a[1]), "r"(a[2]), "r"(a[3]), "r"(b0), "r"(b1));
}
__device__ __forceinline__ void split_f16(float v, __half& h, __half& l) {
    h = __float2half_rn(v);
    l = __float2half_rn(v - __half2float(h));
}
__device__ __forceinline__ uint32_t packh(__half a, __half b) {
    return (uint32_t)__half_as_ushort(a) | ((uint32_t)__half_as_ushort(b) << 16);
}
__device__ __forceinline__ uint32_t packf(float a, float b) {
    return packh(__float2half_rn(a), __float2half_rn(b));
}
__device__ __forceinline__ float ftanh(float x) {
    float y; asm("tanh.approx.f32 %0, %1;" : "=f"(y) : "f"(x)); return y;
}
__device__ __forceinline__ float fsig(float x) {
    float y; asm("tanh.approx.f32 %0, %1;" : "=f"(y) : "f"(0.5f * x));
    return fmaf(0.5f, y, 0.5f);
}

// ---------------- the whole network in one kernel --------------------------
// CTA = 16 batch, 512 threads (16 warps). Warp w owns gate rows
// j in [16w, 16w+16) for ALL GEMMs. Per step t:
//   acc1 = Wih0@x[t] + Whh0@h1[t-1]   (gates1[t], +bias0 in activation)
//   acc2 = Wih1@h1[t-1] + Whh1@h2[t-2] (gates2[t-1], +bias1 in activation)
// x[t+1] is staged (fp32->fp16 pair-packed) during step t into buf (t+1)&1.
__global__ void __launch_bounds__(512, 1) lstm_fused(
    const float* __restrict__ x,      // [B][T][I]
    const float* __restrict__ w_ih0,  // [256][88]
    const float* __restrict__ w_hh0,  // [256][64]
    const float* __restrict__ bi0,    // [256]
    const float* __restrict__ bh0,    // [256]
    const float* __restrict__ w_ih1,  // [256][64]
    const float* __restrict__ w_hh1,  // [256][64]
    const float* __restrict__ bi1,    // [256]
    const float* __restrict__ bh1,    // [256]
    const float* __restrict__ fc_w,   // [O][H]
    const float* __restrict__ fc_b,   // [O]
    float* __restrict__ out)          // [B][O]
{
    extern __shared__ uint32_t smu[];
    uint32_t* hB1 = smu;                       // [32][HBS]   h1 fp16 pairs
    uint32_t* hB2 = smu + 768;                 // [32][HBS]   h2 fp16 pairs
    uint32_t* xB  = smu + 1536;                // [2][48][HBS] x fp16 pairs
    uint32_t* sWD = smu + 1536 + 2 * XBUF;     // [16][512] W_hh1 frags
    uint32_t* sWI = sWD + 16 * 512;            // [24][512] W_ih0 frags
    uint32_t* sG1 = sWI + 24 * 512;            // [256][GS2] packed gates1
    uint32_t* sG2 = sG1 + 256 * GS2;           // [256][GS2] packed gates2
    float* sHL    = (float*)(sG2 + 256 * GS2); // [64][20]

    const int tid = threadIdx.x;
    const int lane = tid & 31, w = tid >> 5;
    const int g = lane >> 2, tg = lane & 3;
    const int batch0 = blockIdx.x * 16;

    // zero h buffers and BOTH x buffers (pad rows stay zero forever)
    for (int i = tid; i < 1536 + 2 * XBUF; i += 512) smu[i] = 0u;

    // static A frags: W_hh0 (a) & W_ih1 (c) split in regs;
    // W_hh1 (sWD) & W_ih0 (sWI) single fp16 in per-thread SMEM caches.
    uint32_t a_h[4][4], a_l[4][4], c_h[4][4], c_l[4][4];
    #pragma unroll
    for (int kk = 0; kk < 4; ++kk) {
        #pragma unroll
        for (int r = 0; r < 4; ++r) {
            const int row = 16 * w + g + (r & 1) * 8;
            const int col = 16 * kk + 2 * tg + (r >> 1) * 8;
            __half h0, l0, h1, l1;
            float2 v = *(const float2*)(w_hh0 + row * 64 + col);
            split_f16(v.x, h0, l0); split_f16(v.y, h1, l1);
            a_h[kk][r] = packh(h0, h1); a_l[kk][r] = packh(l0, l1);
            float2 u = *(const float2*)(w_ih1 + row * 64 + col);
            split_f16(u.x, h0, l0); split_f16(u.y, h1, l1);
            c_h[kk][r] = packh(h0, h1); c_l[kk][r] = packh(l0, l1);
            float2 z = *(const float2*)(w_hh1 + row * 64 + col);
            sWD[(kk * 4 + r) * 512 + tid] =
                packh(__float2half_rn(z.x), __float2half_rn(z.y));
        }
    }
    #pragma unroll
    for (int kk = 0; kk < 6; ++kk) {
        #pragma unroll
        for (int r = 0; r < 4; ++r) {
            const int row = 16 * w + g + (r & 1) * 8;
            const int col = 16 * kk + 2 * tg + (r >> 1) * 8;
            float z0 = (col < I)     ? w_ih0[row * I + col]     : 0.f;
            float z1 = (col + 1 < I) ? w_ih0[row * I + col + 1] : 0.f;
            sWI[(kk * 4 + r) * 512 + tid] =
                packh(__float2half_rn(z0), __float2half_rn(z1));
        }
    }

    // activation roles (R12): one h index, 2 batches
    const int hC = tid & 63;
    const int bC = (tid >> 6) * 2;
    const int gcol = tid >> 6;
    float c1_reg[2] = {0.f, 0.f};
    float c2_reg[2] = {0.f, 0.f};
    float bv0[4], bv1[4];
    #pragma unroll
    for (int p = 0; p < 4; ++p) {
        bv0[p] = bi0[p * 64 + hC] + bh0[p * 64 + hC];
        bv1[p] = bi1[p * 64 + hC] + bh1[p * 64 + hC];
    }

    // x staging roles: element e -> batch e/XP, pair e%XP
    const int e0 = tid, b_0 = e0 / XP, p_0 = e0 - XP * b_0;
    const int e1 = tid + 512, b_1 = e1 / XP, p_1 = e1 - XP * b_1;
    const bool has1 = (e1 < 16 * XP);

    // prologue: stage x[0] into buf 0
    {
        const float* xr = x + ((size_t)(batch0 + b_0) * T + 0) * I + 2 * p_0;
        float2 v = *(const float2*)xr;
        xB[p_0 * HBS + b_0] = packf(v.x, v.y);
        if (has1) {
            const float* xr1 = x + ((size_t)(batch0 + b_1) * T + 0) * I + 2 * p_1;
            float2 v1 = *(const float2*)xr1;
            xB[p_1 * HBS + b_1] = packf(v1.x, v1.y);
        }
    }
    __syncthreads();

    for (int t = 0; t < T; ++t) {
        const uint32_t* xr = xB + (t & 1) * XBUF;
        uint32_t* xw       = xB + ((t + 1) & 1) * XBUF;

        // issue next-step x loads early (consumed after gate store)
        float2 xv0 = make_float2(0.f, 0.f), xv1 = make_float2(0.f, 0.f);
        if (t + 1 < T) {
            xv0 = *(const float2*)(x + ((size_t)(batch0 + b_0) * T + t + 1) * I + 2 * p_0);
            if (has1)
                xv1 = *(const float2*)(x + ((size_t)(batch0 + b_1) * T + t + 1) * I + 2 * p_1);
        }

        float acc1[2][4] = {};
        float acc2[2][4] = {};
        // part 0: gates1 += Wih0 @ x[t]  (single-fp16 frags from sWI)
        #pragma unroll
        for (int kk = 0; kk < 6; ++kk) {
            uint32_t eh[4];
            #pragma unroll
            for (int r = 0; r < 4; ++r)
                eh[r] = sWI[(kk * 4 + r) * 512 + tid];
            #pragma unroll
            for (int nt = 0; nt < 2; ++nt) {
                const int c0 = (8 * kk + tg) * HBS + 8 * nt + g;
                const int c1 = (8 * kk + 4 + tg) * HBS + 8 * nt + g;
                mma16816(acc1[nt], eh, xr[c0], xr[c1]);
            }
        }
        // part 1: B = h1[t-1] feeds acc1 (Whh0 split) and acc2 (Wih1 split)
        #pragma unroll
        for (int kk = 0; kk < 4; ++kk) {
            #pragma unroll
            for (int nt = 0; nt < 2; ++nt) {
                const int c0 = (8 * kk + tg) * HBS + 8 * nt + g;
                const int c1 = (8 * kk + 4 + tg) * HBS + 8 * nt + g;
                const uint32_t b0 = hB1[c0], b1 = hB1[c1];
                mma16816(acc1[nt], a_h[kk], b0, b1);
                mma16816(acc2[nt], c_h[kk], b0, b1);
                mma16816(acc1[nt], a_l[kk], b0, b1);
                mma16816(acc2[nt], c_l[kk], b0, b1);
            }
        }
        // part 2: B = h2[t-2] feeds acc2 (Whh1 single from sWD)
        #pragma unroll
        for (int kk = 0; kk < 4; ++kk) {
            uint32_t dh[4];
            #pragma unroll
            for (int r = 0; r < 4; ++r)
                dh[r] = sWD[(kk * 4 + r) * 512 + tid];
            #pragma unroll
            for (int nt = 0; nt < 2; ++nt) {
                const int c0 = (8 * kk + tg) * HBS + 8 * nt + g;
                const int c1 = (8 * kk + 4 + tg) * HBS + 8 * nt + g;
                mma16816(acc2[nt], dh, hB2[c0], hB2[c1]);
            }
        }
        // store gates packed fp16 + stage x[t+1]
        #pragma unroll
        for (int nt = 0; nt < 2; ++nt) {
            const int col = 4 * nt + tg;
            sG1[(16 * w + g) * GS2 + col]     = packf(acc1[nt][0], acc1[nt][1]);
            sG1[(16 * w + g + 8) * GS2 + col] = packf(acc1[nt][2], acc1[nt][3]);
            sG2[(16 * w + g) * GS2 + col]     = packf(acc2[nt][0], acc2[nt][1]);
            sG2[(16 * w + g + 8) * GS2 + col] = packf(acc2[nt][2], acc2[nt][3]);
        }
        if (t + 1 < T) {
            xw[p_0 * HBS + b_0] = packf(xv0.x, xv0.y);
            if (has1) xw[p_1 * HBS + b_1] = packf(xv1.x, xv1.y);
        }
        __syncthreads();   // BAR1: gates visible; hB/xB reads done

        // activation L1: h1[t]
        float2 G[4];
        #pragma unroll
        for (int p = 0; p < 4; ++p) {
            uint32_t u = sG1[(hC + 64 * p) * GS2 + gcol];
            G[p] = __half22float2(*(__half2*)&u);
        }
        #pragma unroll
        for (int q = 0; q < 2; ++q) {
            float gi = (q ? G[0].y : G[0].x) + bv0[0];
            float gf = (q ? G[1].y : G[1].x) + bv0[1];
            float gg = (q ? G[2].y : G[2].x) + bv0[2];
            float go = (q ? G[3].y : G[3].x) + bv0[3];
            gi = fsig(gi); gf = fsig(gf); go = fsig(go); gg = ftanh(gg);
            const float c = gf * c1_reg[q] + gi * gg;
            c1_reg[q] = c;
            const float hv = go * ftanh(c);
            ((unsigned short*)hB1)[((hC >> 1) * HBS + bC + q) * 2 + (hC & 1)] =
                __half_as_ushort(__float2half_rn(hv));
        }
        // activation L2: h2[t-1] (skip at t=0)
        if (t >= 1) {
            #pragma unroll
            for (int p = 0; p < 4; ++p) {
                uint32_t u = sG2[(hC + 64 * p) * GS2 + gcol];
                G[p] = __half22float2(*(__half2*)&u);
            }
            #pragma unroll
            for (int q = 0; q < 2; ++q) {
                float gi = (q ? G[0].y : G[0].x) + bv1[0];
                float gf = (q ? G[1].y : G[1].x) + bv1[1];
                float gg = (q ? G[2].y : G[2].x) + bv1[2];
                float go = (q ? G[3].y : G[3].x) + bv1[3];
                gi = fsig(gi); gf = fsig(gf); go = fsig(go); gg = ftanh(gg);
                const float c = gf * c2_reg[q] + gi * gg;
                c2_reg[q] = c;
                const float hv = go * ftanh(c);
                ((unsigned short*)hB2)[((hC >> 1) * HBS + bC + q) * 2 + (hC & 1)] =
                    __half_as_ushort(__float2half_rn(hv));
            }
        }
        __syncthreads();   // BAR2: h/x writes visible for next step
    }

    // epilogue: gates2[T-1] from h1[T-1] and h2[T-2] -> h2[T-1]
    {
        float acc2[2][4] = {};
        #pragma unroll
        for (int kk = 0; kk < 4; ++kk) {
            uint32_t dh[4];
            #pragma unroll
            for (int r = 0; r < 4; ++r)
                dh[r] = sWD[(kk * 4 + r) * 512 + tid];
            #pragma unroll
            for (int nt = 0; nt < 2; ++nt) {
                const int c0 = (8 * kk + tg) * HBS + 8 * nt + g;
                const int c1 = (8 * kk + 4 + tg) * HBS + 8 * nt + g;
                const uint32_t b0 = hB1[c0], b1 = hB1[c1];
                mma16816(acc2[nt], c_h[kk], b0, b1);
                mma16816(acc2[nt], c_l[kk], b0, b1);
                mma16816(acc2[nt], dh, hB2[c0], hB2[c1]);
            }
        }
        #pragma unroll
        for (int nt = 0; nt < 2; ++nt) {
            const int col = 4 * nt + tg;
            sG2[(16 * w + g) * GS2 + col]     = packf(acc2[nt][0], acc2[nt][1]);
            sG2[(16 * w + g + 8) * GS2 + col] = packf(acc2[nt][2], acc2[nt][3]);
        }
        __syncthreads();

        float2 G[4];
        #pragma unroll
        for (int p = 0; p < 4; ++p) {
            uint32_t u = sG2[(hC + 64 * p) * GS2 + gcol];
            G[p] = __half22float2(*(__half2*)&u);
        }
        #pragma unroll
        for (int q = 0; q < 2; ++q) {
            float gi = (q ? G[0].y : G[0].x) + bv1[0];
            float gf = (q ? G[1].y : G[1].x) + bv1[1];
            float gg = (q ? G[2].y : G[2].x) + bv1[2];
            float go = (q ? G[3].y : G[3].x) + bv1[3];
            gi = fsig(gi); gf = fsig(gf); go = fsig(go); gg = ftanh(gg);
            const float c = gf * c2_reg[q] + gi * gg;
            sHL[hC * 20 + bC + q] = go * ftanh(c);
        }
        __syncthreads();
    }

    // FC head: out = h2_last @ fc_w^T + fc_b
    for (int idx = tid; idx < 16 * O; idx += 512) {
        int b = idx / O, o = idx - (idx / O) * O;
        float sum = fc_b[o];
        #pragma unroll
        for (int hh = 0; hh < H; ++hh)
            sum += sHL[hh * 20 + b] * fc_w[o * H + hh];
        out[(batch0 + b) * O + o] = sum;
    }
}

extern "C" void kernel_launch(void* const* d_in, const int* in_sizes, int n_in,
                              void* d_out, int out_size) {
    const float* x     = (const float*)d_in[0];
    const float* w_ih0 = (const float*)d_in[1];
    const float* w_hh0 = (const float*)d_in[2];
    const float* b_ih0 = (const float*)d_in[3];
    const float* b_hh0 = (const float*)d_in[4];
    const float* w_ih1 = (const float*)d_in[5];
    const float* w_hh1 = (const float*)d_in[6];
    const float* b_ih1 = (const float*)d_in[7];
    const float* b_hh1 = (const float*)d_in[8];
    const float* fc_w  = (const float*)d_in[9];
    const float* fc_b  = (const float*)d_in[10];
    float* out = (float*)d_out;

    // smem words: 1536(hB) + 2304(xB) + 8192(sWD) + 12288(sWI)
    //           + 2*256*GS2(gates) + 320(sHL)
    const int smR = (1536 + 2 * XBUF + 16 * 512 + 24 * 512
                     + 2 * 256 * GS2 + 64 * 20) * 4 + 256;

    cudaFuncSetAttribute(lstm_fused,
                         cudaFuncAttributeMaxDynamicSharedMemorySize, smR);

    lstm_fused<<<B / 16, 512, smR>>>(
        x, w_ih0, w_hh0, b_ih0, b_hh0,
        w_ih1, w_hh1, b_ih1, b_hh1, fc_w, fc_b, out);
}

// round 16
// speedup vs baseline: 1.5743x; 1.1769x over previous
#include <cuda_runtime.h>
#include <cuda_fp16.h>
#include <cstdint>
#include <math.h>

// MusicRNN: 2-layer LSTM (B=2048, T=256, I=88, H=64) + FC (O=13).
// R15 (on R14's single-kernel design):
//  - ALL weights single fp16 (W_hh0, W_ih1 unsplit): 52 -> 36 MMAs/warp/step;
//    W_hh1 frags move to registers (sWD smem cache deleted).
//  - acc1 split into x-part and h-part accumulators (shorter MMA chains).
//  - activation in f16x2 via tanh.approx.f16x2: 20 -> 10 MUFU/thread/step;
//    c state stays fp32 (compounding path keeps precision).

namespace {
constexpr int B = 2048, T = 256, I = 88, H = 64, O = 13, G4 = 256;
constexpr int HBS = 24;                      // hB / xB row stride (words)
constexpr int GS2 = 13;                      // packed gate row stride (words)
constexpr int XP  = 44;                      // x pair-words per batch (88/2)
constexpr int XBUF = 48 * HBS;               // 1152 words per x buffer
}

// ---------------- helpers (baseline PTX only) ------------------------------
__device__ __forceinline__ void mma16816(float* c, const uint32_t* a,
                                         uint32_t b0, uint32_t b1) {
    asm volatile(
        "mma.sync.aligned.m16n8k16.row.col.f32.f16.f16.f32 "
        "{%0,%1,%2,%3}, {%4,%5,%6,%7}, {%8,%9}, {%0,%1,%2,%3};"
        : "+f"(c[0]), "+f"(c[1]), "+f"(c[2]), "+f"(c[3])
        : "r"(a[0]), "r"(a[1]), "r"(a[2]), "r"(a[3]), "r"(b0), "r"(b1));
}
__device__ __forceinline__ uint32_t packh(__half a, __half b) {
    return (uint32_t)__half_as_ushort(a) | ((uint32_t)__half_as_ushort(b) << 16);
}
__device__ __forceinline__ uint32_t packf(float a, float b) {
    return packh(__float2half_rn(a), __float2half_rn(b));
}
__device__ __forceinline__ __half2 tanh2(__half2 x) {
    uint32_t y, xi = *(uint32_t*)&x;
    asm("tanh.approx.f16x2 %0, %1;" : "=r"(y) : "r"(xi));
    return *(__half2*)&y;
}
__device__ __forceinline__ float ftanh(float x) {
    float y; asm("tanh.approx.f32 %0, %1;" : "=f"(y) : "f"(x)); return y;
}
__device__ __forceinline__ float fsig(float x) {
    float y; asm("tanh.approx.f32 %0, %1;" : "=f"(y) : "f"(0.5f * x));
    return fmaf(0.5f, y, 0.5f);
}

// ---------------- the whole network in one kernel --------------------------
// CTA = 16 batch, 512 threads (16 warps). Warp w owns gate rows
// j in [16w, 16w+16) for ALL GEMMs. Per step t:
//   gates1[t]   = Wih0@x[t] (acc1x) + Whh0@h1[t-1] (acc1h)  [+bias0]
//   gates2[t-1] = Wih1@h1[t-1] + Whh1@h2[t-2] (acc2)        [+bias1]
__global__ void __launch_bounds__(512, 1) lstm_fused(
    const float* __restrict__ x,      // [B][T][I]
    const float* __restrict__ w_ih0,  // [256][88]
    const float* __restrict__ w_hh0,  // [256][64]
    const float* __restrict__ bi0,    // [256]
    const float* __restrict__ bh0,    // [256]
    const float* __restrict__ w_ih1,  // [256][64]
    const float* __restrict__ w_hh1,  // [256][64]
    const float* __restrict__ bi1,    // [256]
    const float* __restrict__ bh1,    // [256]
    const float* __restrict__ fc_w,   // [O][H]
    const float* __restrict__ fc_b,   // [O]
    float* __restrict__ out)          // [B][O]
{
    extern __shared__ uint32_t smu[];
    uint32_t* hB1 = smu;                       // [32][HBS]   h1 fp16 pairs
    uint32_t* hB2 = smu + 768;                 // [32][HBS]   h2 fp16 pairs
    uint32_t* xB  = smu + 1536;                // [2][48][HBS] x fp16 pairs
    uint32_t* sWI = smu + 1536 + 2 * XBUF;     // [24][512] W_ih0 frags
    uint32_t* sG1 = sWI + 24 * 512;            // [256][GS2] packed gates1
    uint32_t* sG2 = sG1 + 256 * GS2;           // [256][GS2] packed gates2
    float* sHL    = (float*)(sG2 + 256 * GS2); // [64][20]

    const int tid = threadIdx.x;
    const int lane = tid & 31, w = tid >> 5;
    const int g = lane >> 2, tg = lane & 3;
    const int batch0 = blockIdx.x * 16;

    // zero h buffers and BOTH x buffers (pad rows stay zero forever)
    for (int i = tid; i < 1536 + 2 * XBUF; i += 512) smu[i] = 0u;

    // static A frags, ALL single fp16: Whh0 (a), Wih1 (c), Whh1 (d) in regs;
    // Wih0 in per-thread SMEM cache (sWI).
    uint32_t a[4][4], c[4][4], d[4][4];
    #pragma unroll
    for (int kk = 0; kk < 4; ++kk) {
        #pragma unroll
        for (int r = 0; r < 4; ++r) {
            const int row = 16 * w + g + (r & 1) * 8;
            const int col = 16 * kk + 2 * tg + (r >> 1) * 8;
            float2 v = *(const float2*)(w_hh0 + row * 64 + col);
            a[kk][r] = packf(v.x, v.y);
            float2 u = *(const float2*)(w_ih1 + row * 64 + col);
            c[kk][r] = packf(u.x, u.y);
            float2 z = *(const float2*)(w_hh1 + row * 64 + col);
            d[kk][r] = packf(z.x, z.y);
        }
    }
    #pragma unroll
    for (int kk = 0; kk < 6; ++kk) {
        #pragma unroll
        for (int r = 0; r < 4; ++r) {
            const int row = 16 * w + g + (r & 1) * 8;
            const int col = 16 * kk + 2 * tg + (r >> 1) * 8;
            float z0 = (col < I)     ? w_ih0[row * I + col]     : 0.f;
            float z1 = (col + 1 < I) ? w_ih0[row * I + col + 1] : 0.f;
            sWI[(kk * 4 + r) * 512 + tid] = packf(z0, z1);
        }
    }

    // activation roles: one h index, 2 batches (half2-paired along batch)
    const int hC = tid & 63;
    const int bC = (tid >> 6) * 2;
    const int gcol = tid >> 6;
    float c1_reg[2] = {0.f, 0.f};
    float c2_reg[2] = {0.f, 0.f};
    const __half2 h05 = __float2half2_rn(0.5f);
    __half2 bv0h[4], bv1h[4];
    float bv1f[4];
    #pragma unroll
    for (int p = 0; p < 4; ++p) {
        float b0v = bi0[p * 64 + hC] + bh0[p * 64 + hC];
        float b1v = bi1[p * 64 + hC] + bh1[p * 64 + hC];
        bv0h[p] = __float2half2_rn(b0v);
        bv1h[p] = __float2half2_rn(b1v);
        bv1f[p] = b1v;
    }

    // x staging roles: element e -> batch e/XP, pair e%XP
    const int e0 = tid, b_0 = e0 / XP, p_0 = e0 - XP * b_0;
    const int e1 = tid + 512, b_1 = e1 / XP, p_1 = e1 - XP * b_1;
    const bool has1 = (e1 < 16 * XP);

    // prologue: stage x[0] into buf 0
    {
        float2 v = *(const float2*)(x + ((size_t)(batch0 + b_0) * T) * I + 2 * p_0);
        xB[p_0 * HBS + b_0] = packf(v.x, v.y);
        if (has1) {
            float2 v1 = *(const float2*)(x + ((size_t)(batch0 + b_1) * T) * I + 2 * p_1);
            xB[p_1 * HBS + b_1] = packf(v1.x, v1.y);
        }
    }
    __syncthreads();

    for (int t = 0; t < T; ++t) {
        const uint32_t* xr = xB + (t & 1) * XBUF;
        uint32_t* xw       = xB + ((t + 1) & 1) * XBUF;

        // issue next-step x loads early (consumed after gate store)
        float2 xv0 = make_float2(0.f, 0.f), xv1 = make_float2(0.f, 0.f);
        if (t + 1 < T) {
            xv0 = *(const float2*)(x + ((size_t)(batch0 + b_0) * T + t + 1) * I + 2 * p_0);
            if (has1)
                xv1 = *(const float2*)(x + ((size_t)(batch0 + b_1) * T + t + 1) * I + 2 * p_1);
        }

        float acc1x[2][4] = {};
        float acc1h[2][4] = {};
        float acc2[2][4] = {};
        // part 0: acc1x = Wih0 @ x[t]  (frags from sWI)
        #pragma unroll
        for (int kk = 0; kk < 6; ++kk) {
            uint32_t eh[4];
            #pragma unroll
            for (int r = 0; r < 4; ++r)
                eh[r] = sWI[(kk * 4 + r) * 512 + tid];
            #pragma unroll
            for (int nt = 0; nt < 2; ++nt) {
                const int c0 = (8 * kk + tg) * HBS + 8 * nt + g;
                const int c1 = (8 * kk + 4 + tg) * HBS + 8 * nt + g;
                mma16816(acc1x[nt], eh, xr[c0], xr[c1]);
            }
        }
        // part 1: B = h1[t-1] feeds acc1h (Whh0) and acc2 (Wih1)
        #pragma unroll
        for (int kk = 0; kk < 4; ++kk) {
            #pragma unroll
            for (int nt = 0; nt < 2; ++nt) {
                const int c0 = (8 * kk + tg) * HBS + 8 * nt + g;
                const int c1 = (8 * kk + 4 + tg) * HBS + 8 * nt + g;
                const uint32_t b0 = hB1[c0], b1 = hB1[c1];
                mma16816(acc1h[nt], a[kk], b0, b1);
                mma16816(acc2[nt], c[kk], b0, b1);
            }
        }
        // part 2: B = h2[t-2] feeds acc2 (Whh1 from regs)
        #pragma unroll
        for (int kk = 0; kk < 4; ++kk) {
            #pragma unroll
            for (int nt = 0; nt < 2; ++nt) {
                const int c0 = (8 * kk + tg) * HBS + 8 * nt + g;
                const int c1 = (8 * kk + 4 + tg) * HBS + 8 * nt + g;
                mma16816(acc2[nt], d[kk], hB2[c0], hB2[c1]);
            }
        }
        // store gates packed fp16 + stage x[t+1]
        #pragma unroll
        for (int nt = 0; nt < 2; ++nt) {
            const int col = 4 * nt + tg;
            sG1[(16 * w + g) * GS2 + col] =
                packf(acc1x[nt][0] + acc1h[nt][0], acc1x[nt][1] + acc1h[nt][1]);
            sG1[(16 * w + g + 8) * GS2 + col] =
                packf(acc1x[nt][2] + acc1h[nt][2], acc1x[nt][3] + acc1h[nt][3]);
            sG2[(16 * w + g) * GS2 + col]     = packf(acc2[nt][0], acc2[nt][1]);
            sG2[(16 * w + g + 8) * GS2 + col] = packf(acc2[nt][2], acc2[nt][3]);
        }
        if (t + 1 < T) {
            xw[p_0 * HBS + b_0] = packf(xv0.x, xv0.y);
            if (has1) xw[p_1 * HBS + b_1] = packf(xv1.x, xv1.y);
        }
        __syncthreads();   // BAR1: gates visible; hB/xB reads done

        // ---- activation L1 (f16x2): h1[t]
        {
            __half2 G[4];
            #pragma unroll
            for (int p = 0; p < 4; ++p) {
                uint32_t u = sG1[(hC + 64 * p) * GS2 + gcol];
                G[p] = *(__half2*)&u;
            }
            __half2 t2;
            t2 = tanh2(__hmul2(__hadd2(G[0], bv0h[0]), h05));
            __half2 i2 = __hfma2(t2, h05, h05);
            t2 = tanh2(__hmul2(__hadd2(G[1], bv0h[1]), h05));
            __half2 f2 = __hfma2(t2, h05, h05);
            __half2 g2 = tanh2(__hadd2(G[2], bv0h[2]));
            t2 = tanh2(__hmul2(__hadd2(G[3], bv0h[3]), h05));
            __half2 o2 = __hfma2(t2, h05, h05);
            float2 fi = __half22float2(i2);
            float2 ff = __half22float2(f2);
            float2 fg = __half22float2(g2);
            c1_reg[0] = ff.x * c1_reg[0] + fi.x * fg.x;
            c1_reg[1] = ff.y * c1_reg[1] + fi.y * fg.y;
            __half2 h2v = __hmul2(o2, tanh2(__floats2half2_rn(c1_reg[0], c1_reg[1])));
            const int base = ((hC >> 1) * HBS) * 2 + (hC & 1);
            ((unsigned short*)hB1)[base + 2 * bC] =
                __half_as_ushort(__low2half(h2v));
            ((unsigned short*)hB1)[base + 2 * (bC + 1)] =
                __half_as_ushort(__high2half(h2v));
        }
        // ---- activation L2 (f16x2): h2[t-1] (skip at t=0)
        if (t >= 1) {
            __half2 G[4];
            #pragma unroll
            for (int p = 0; p < 4; ++p) {
                uint32_t u = sG2[(hC + 64 * p) * GS2 + gcol];
                G[p] = *(__half2*)&u;
            }
            __half2 t2;
            t2 = tanh2(__hmul2(__hadd2(G[0], bv1h[0]), h05));
            __half2 i2 = __hfma2(t2, h05, h05);
            t2 = tanh2(__hmul2(__hadd2(G[1], bv1h[1]), h05));
            __half2 f2 = __hfma2(t2, h05, h05);
            __half2 g2 = tanh2(__hadd2(G[2], bv1h[2]));
            t2 = tanh2(__hmul2(__hadd2(G[3], bv1h[3]), h05));
            __half2 o2 = __hfma2(t2, h05, h05);
            float2 fi = __half22float2(i2);
            float2 ff = __half22float2(f2);
            float2 fg = __half22float2(g2);
            c2_reg[0] = ff.x * c2_reg[0] + fi.x * fg.x;
            c2_reg[1] = ff.y * c2_reg[1] + fi.y * fg.y;
            __half2 h2v = __hmul2(o2, tanh2(__floats2half2_rn(c2_reg[0], c2_reg[1])));
            const int base = ((hC >> 1) * HBS) * 2 + (hC & 1);
            ((unsigned short*)hB2)[base + 2 * bC] =
                __half_as_ushort(__low2half(h2v));
            ((unsigned short*)hB2)[base + 2 * (bC + 1)] =
                __half_as_ushort(__high2half(h2v));
        }
        __syncthreads();   // BAR2: h/x writes visible for next step
    }

    // epilogue: gates2[T-1] from h1[T-1] and h2[T-2] -> h2[T-1] (fp32 path)
    {
        float acc2[2][4] = {};
        #pragma unroll
        for (int kk = 0; kk < 4; ++kk) {
            #pragma unroll
            for (int nt = 0; nt < 2; ++nt) {
                const int c0 = (8 * kk + tg) * HBS + 8 * nt + g;
                const int c1 = (8 * kk + 4 + tg) * HBS + 8 * nt + g;
                mma16816(acc2[nt], c[kk], hB1[c0], hB1[c1]);
                mma16816(acc2[nt], d[kk], hB2[c0], hB2[c1]);
            }
        }
        #pragma unroll
        for (int nt = 0; nt < 2; ++nt) {
            const int col = 4 * nt + tg;
            sG2[(16 * w + g) * GS2 + col]     = packf(acc2[nt][0], acc2[nt][1]);
            sG2[(16 * w + g + 8) * GS2 + col] = packf(acc2[nt][2], acc2[nt][3]);
        }
        __syncthreads();

        #pragma unroll
        for (int q = 0; q < 2; ++q) {
            float G[4];
            #pragma unroll
            for (int p = 0; p < 4; ++p) {
                uint32_t u = sG2[(hC + 64 * p) * GS2 + gcol];
                __half2 hv = *(__half2*)&u;
                G[p] = q ? __half2float(__high2half(hv))
                         : __half2float(__low2half(hv));
            }
            float gi = fsig(G[0] + bv1f[0]);
            float gf = fsig(G[1] + bv1f[1]);
            float gg = ftanh(G[2] + bv1f[2]);
            float go = fsig(G[3] + bv1f[3]);
            const float cc = gf * c2_reg[q] + gi * gg;
            sHL[hC * 20 + bC + q] = go * ftanh(cc);
        }
        __syncthreads();
    }

    // FC head: out = h2_last @ fc_w^T + fc_b
    for (int idx = tid; idx < 16 * O; idx += 512) {
        int b = idx / O, o = idx - (idx / O) * O;
        float sum = fc_b[o];
        #pragma unroll
        for (int hh = 0; hh < H; ++hh)
            sum += sHL[hh * 20 + b] * fc_w[o * H + hh];
        out[(batch0 + b) * O + o] = sum;
    }
}

extern "C" void kernel_launch(void* const* d_in, const int* in_sizes, int n_in,
                              void* d_out, int out_size) {
    const float* x     = (const float*)d_in[0];
    const float* w_ih0 = (const float*)d_in[1];
    const float* w_hh0 = (const float*)d_in[2];
    const float* b_ih0 = (const float*)d_in[3];
    const float* b_hh0 = (const float*)d_in[4];
    const float* w_ih1 = (const float*)d_in[5];
    const float* w_hh1 = (const float*)d_in[6];
    const float* b_ih1 = (const float*)d_in[7];
    const float* b_hh1 = (const float*)d_in[8];
    const float* fc_w  = (const float*)d_in[9];
    const float* fc_b  = (const float*)d_in[10];
    float* out = (float*)d_out;

    // smem words: 1536(hB) + 2304(xB) + 12288(sWI) + 2*256*GS2 + 320(sHL)
    const int smR = (1536 + 2 * XBUF + 24 * 512
                     + 2 * 256 * GS2 + 64 * 20) * 4 + 256;

    cudaFuncSetAttribute(lstm_fused,
                         cudaFuncAttributeMaxDynamicSharedMemorySize, smR);

    lstm_fused<<<B / 16, 512, smR>>>(
        x, w_ih0, w_hh0, b_ih0, b_hh0,
        w_ih1, w_hh1, b_ih1, b_hh1, fc_w, fc_b, out);
}

// round 17
// speedup vs baseline: 1.7958x; 1.1407x over previous
#include <cuda_runtime.h>
#include <cuda_fp16.h>
#include <cstdint>
#include <math.h>

// MusicRNN: 2-layer LSTM (B=2048, T=256, I=88, H=64) + FC (O=13).
// R16 = R15 with pure LAYOUT changes (bit-identical math):
//  - hB/xB pair-interleaved so each MMA B-fragment is ONE LDS.64
//    (row stride 40 words -> conflict-free 2-phase access).
//  - sWI A-frag cache pair-packed -> LDS.64, conflict-free.
//  - packf via cvt.rn.f16x2.f32 (single F2FP).
// LDS/warp/step: 88 -> 48. Everything else identical to R15.

namespace {
constexpr int B = 2048, T = 256, I = 88, H = 64, O = 13;
constexpr int HS = 40;                  // row stride (words) hB/xB
constexpr int HWORDS = 16 * HS;         // 640 words per h buffer
constexpr int XWORDS = 24 * HS;         // 960 words per x buffer
constexpr int GS2 = 13;                 // packed gate row stride (words)
constexpr int XP = 44;                  // x pair-words per batch (88/2)
}

// ---------------- helpers (baseline PTX only) ------------------------------
__device__ __forceinline__ void mma16816(float* c, const uint32_t* a,
                                         uint32_t b0, uint32_t b1) {
    asm volatile(
        "mma.sync.aligned.m16n8k16.row.col.f32.f16.f16.f32 "
        "{%0,%1,%2,%3}, {%4,%5,%6,%7}, {%8,%9}, {%0,%1,%2,%3};"
        : "+f"(c[0]), "+f"(c[1]), "+f"(c[2]), "+f"(c[3])
        : "r"(a[0]), "r"(a[1]), "r"(a[2]), "r"(a[3]), "r"(b0), "r"(b1));
}
__device__ __forceinline__ uint32_t packf(float a, float b) {
    __half2 h = __floats2half2_rn(a, b);   // single F2FP.PACK
    return *(uint32_t*)&h;
}
__device__ __forceinline__ __half2 tanh2(__half2 x) {
    uint32_t y, xi = *(uint32_t*)&x;
    asm("tanh.approx.f16x2 %0, %1;" : "=r"(y) : "r"(xi));
    return *(__half2*)&y;
}
__device__ __forceinline__ float ftanh(float x) {
    float y; asm("tanh.approx.f32 %0, %1;" : "=f"(y) : "f"(x)); return y;
}
__device__ __forceinline__ float fsig(float x) {
    float y; asm("tanh.approx.f32 %0, %1;" : "=f"(y) : "f"(0.5f * x));
    return fmaf(0.5f, y, 0.5f);
}
// pair-interleaved word address for k-pair p, batch b:
// kk=p>>3, hi=(p>>2)&1, tg=p&3 -> row=(kk*4+tg), addr=row*HS + b*2 + hi
__device__ __forceinline__ int bword(int p, int b) {
    return ((p >> 3) * 4 + (p & 3)) * HS + b * 2 + ((p >> 2) & 1);
}

// ---------------- the whole network in one kernel --------------------------
__global__ void __launch_bounds__(512, 1) lstm_fused(
    const float* __restrict__ x,      // [B][T][I]
    const float* __restrict__ w_ih0,  // [256][88]
    const float* __restrict__ w_hh0,  // [256][64]
    const float* __restrict__ bi0,    // [256]
    const float* __restrict__ bh0,    // [256]
    const float* __restrict__ w_ih1,  // [256][64]
    const float* __restrict__ w_hh1,  // [256][64]
    const float* __restrict__ bi1,    // [256]
    const float* __restrict__ bh1,    // [256]
    const float* __restrict__ fc_w,   // [O][H]
    const float* __restrict__ fc_b,   // [O]
    float* __restrict__ out)          // [B][O]
{
    extern __shared__ uint32_t smu[];
    uint32_t* hB1 = smu;                        // [16][HS] h1 (pair-interleaved)
    uint32_t* hB2 = smu + HWORDS;               // [16][HS] h2
    uint32_t* xB  = smu + 2 * HWORDS;           // [2][24][HS] x
    uint32_t* sWI = xB + 2 * XWORDS;            // [12][1024] W_ih0 frag pairs
    uint32_t* sG1 = sWI + 12 * 1024;            // [256][GS2] packed gates1
    uint32_t* sG2 = sG1 + 256 * GS2;            // [256][GS2] packed gates2
    float* sHL    = (float*)(sG2 + 256 * GS2);  // [64][20]

    const int tid = threadIdx.x;
    const int lane = tid & 31, w = tid >> 5;
    const int g = lane >> 2, tg = lane & 3;
    const int batch0 = blockIdx.x * 16;

    // zero h buffers and BOTH x buffers (pads stay zero forever)
    for (int i = tid; i < 2 * HWORDS + 2 * XWORDS; i += 512) smu[i] = 0u;

    // static A frags, ALL single fp16: Whh0 (a), Wih1 (c), Whh1 (d) in regs;
    // Wih0 pair-packed into sWI.
    uint32_t a[4][4], c[4][4], d[4][4];
    #pragma unroll
    for (int kk = 0; kk < 4; ++kk) {
        #pragma unroll
        for (int r = 0; r < 4; ++r) {
            const int row = 16 * w + g + (r & 1) * 8;
            const int col = 16 * kk + 2 * tg + (r >> 1) * 8;
            float2 v = *(const float2*)(w_hh0 + row * 64 + col);
            a[kk][r] = packf(v.x, v.y);
            float2 u = *(const float2*)(w_ih1 + row * 64 + col);
            c[kk][r] = packf(u.x, u.y);
            float2 z = *(const float2*)(w_hh1 + row * 64 + col);
            d[kk][r] = packf(z.x, z.y);
        }
    }
    #pragma unroll
    for (int kk = 0; kk < 6; ++kk) {
        #pragma unroll
        for (int r = 0; r < 4; ++r) {
            const int row = 16 * w + g + (r & 1) * 8;
            const int col = 16 * kk + 2 * tg + (r >> 1) * 8;
            float z0 = (col < I)     ? w_ih0[row * I + col]     : 0.f;
            float z1 = (col + 1 < I) ? w_ih0[row * I + col + 1] : 0.f;
            // pair-packed: (r0,r1) at half 0, (r2,r3) at half 1
            sWI[(kk * 2 + (r >> 1)) * 1024 + 2 * tid + (r & 1)] = packf(z0, z1);
        }
    }

    // activation roles: one h index, 2 batches
    const int hC = tid & 63;
    const int bC = (tid >> 6) * 2;
    const int gcol = tid >> 6;
    float c1_reg[2] = {0.f, 0.f};
    float c2_reg[2] = {0.f, 0.f};
    const __half2 h05 = __float2half2_rn(0.5f);
    __half2 bv0h[4], bv1h[4];
    float bv1f[4];
    #pragma unroll
    for (int p = 0; p < 4; ++p) {
        float b0v = bi0[p * 64 + hC] + bh0[p * 64 + hC];
        float b1v = bi1[p * 64 + hC] + bh1[p * 64 + hC];
        bv0h[p] = __float2half2_rn(b0v);
        bv1h[p] = __float2half2_rn(b1v);
        bv1f[p] = b1v;
    }
    // h-store half-index pieces (pair-interleaved target)
    const int hrow = ((hC >> 4) * 4 + ((hC >> 1) & 3)) * HS + ((hC >> 3) & 1);
    // ^ p = hC>>1: kk=p>>3=hC>>4, tg=p&3=(hC>>1)&3, hi=(p>>2)&1=(hC>>3)&1

    // x staging roles: element e -> batch e/XP, pair e%XP
    const int e0 = tid, b_0 = e0 / XP, p_0 = e0 - XP * b_0;
    const int e1 = tid + 512, b_1 = e1 / XP, p_1 = e1 - XP * b_1;
    const bool has1 = (e1 < 16 * XP);
    const int xw0 = bword(p_0, b_0);
    const int xw1 = has1 ? bword(p_1, b_1) : 0;

    // prologue: stage x[0] into buf 0
    {
        float2 v = *(const float2*)(x + ((size_t)(batch0 + b_0) * T) * I + 2 * p_0);
        xB[xw0] = packf(v.x, v.y);
        if (has1) {
            float2 v1 = *(const float2*)(x + ((size_t)(batch0 + b_1) * T) * I + 2 * p_1);
            xB[xw1] = packf(v1.x, v1.y);
        }
    }
    __syncthreads();

    // per-lane B-frag base offset (shared by x/h buffers)
    const int bb = tg * HS + g * 2;

    for (int t = 0; t < T; ++t) {
        const uint32_t* xr = xB + (t & 1) * XWORDS;
        uint32_t* xwb      = xB + ((t + 1) & 1) * XWORDS;

        // issue next-step x loads early (consumed after gate store)
        float2 xv0 = make_float2(0.f, 0.f), xv1 = make_float2(0.f, 0.f);
        if (t + 1 < T) {
            xv0 = *(const float2*)(x + ((size_t)(batch0 + b_0) * T + t + 1) * I + 2 * p_0);
            if (has1)
                xv1 = *(const float2*)(x + ((size_t)(batch0 + b_1) * T + t + 1) * I + 2 * p_1);
        }

        float acc1x[2][4] = {};
        float acc1h[2][4] = {};
        float acc2[2][4] = {};
        // part 0: acc1x = Wih0 @ x[t]  (LDS.64 frags)
        #pragma unroll
        for (int kk = 0; kk < 6; ++kk) {
            uint32_t eh[4];
            uint2 e01 = *(const uint2*)(sWI + (kk * 2) * 1024 + 2 * tid);
            uint2 e23 = *(const uint2*)(sWI + (kk * 2 + 1) * 1024 + 2 * tid);
            eh[0] = e01.x; eh[1] = e01.y; eh[2] = e23.x; eh[3] = e23.y;
            #pragma unroll
            for (int nt = 0; nt < 2; ++nt) {
                uint2 bv = *(const uint2*)(xr + bb + kk * 4 * HS + nt * 16);
                mma16816(acc1x[nt], eh, bv.x, bv.y);
            }
        }
        // part 1: B = h1[t-1] feeds acc1h (Whh0) and acc2 (Wih1)
        #pragma unroll
        for (int kk = 0; kk < 4; ++kk) {
            #pragma unroll
            for (int nt = 0; nt < 2; ++nt) {
                uint2 bv = *(const uint2*)(hB1 + bb + kk * 4 * HS + nt * 16);
                mma16816(acc1h[nt], a[kk], bv.x, bv.y);
                mma16816(acc2[nt], c[kk], bv.x, bv.y);
            }
        }
        // part 2: B = h2[t-2] feeds acc2 (Whh1)
        #pragma unroll
        for (int kk = 0; kk < 4; ++kk) {
            #pragma unroll
            for (int nt = 0; nt < 2; ++nt) {
                uint2 bv = *(const uint2*)(hB2 + bb + kk * 4 * HS + nt * 16);
                mma16816(acc2[nt], d[kk], bv.x, bv.y);
            }
        }
        // store gates packed fp16 + stage x[t+1]
        #pragma unroll
        for (int nt = 0; nt < 2; ++nt) {
            const int col = 4 * nt + tg;
            sG1[(16 * w + g) * GS2 + col] =
                packf(acc1x[nt][0] + acc1h[nt][0], acc1x[nt][1] + acc1h[nt][1]);
            sG1[(16 * w + g + 8) * GS2 + col] =
                packf(acc1x[nt][2] + acc1h[nt][2], acc1x[nt][3] + acc1h[nt][3]);
            sG2[(16 * w + g) * GS2 + col]     = packf(acc2[nt][0], acc2[nt][1]);
            sG2[(16 * w + g + 8) * GS2 + col] = packf(acc2[nt][2], acc2[nt][3]);
        }
        if (t + 1 < T) {
            xwb[xw0] = packf(xv0.x, xv0.y);
            if (has1) xwb[xw1] = packf(xv1.x, xv1.y);
        }
        __syncthreads();   // BAR1: gates visible; hB/xB reads done

        // ---- activation L1 (f16x2): h1[t]
        {
            __half2 G[4];
            #pragma unroll
            for (int p = 0; p < 4; ++p) {
                uint32_t u = sG1[(hC + 64 * p) * GS2 + gcol];
                G[p] = *(__half2*)&u;
            }
            __half2 t2;
            t2 = tanh2(__hmul2(__hadd2(G[0], bv0h[0]), h05));
            __half2 i2 = __hfma2(t2, h05, h05);
            t2 = tanh2(__hmul2(__hadd2(G[1], bv0h[1]), h05));
            __half2 f2 = __hfma2(t2, h05, h05);
            __half2 g2 = tanh2(__hadd2(G[2], bv0h[2]));
            t2 = tanh2(__hmul2(__hadd2(G[3], bv0h[3]), h05));
            __half2 o2 = __hfma2(t2, h05, h05);
            float2 fi = __half22float2(i2);
            float2 ff = __half22float2(f2);
            float2 fg = __half22float2(g2);
            c1_reg[0] = ff.x * c1_reg[0] + fi.x * fg.x;
            c1_reg[1] = ff.y * c1_reg[1] + fi.y * fg.y;
            __half2 h2v = __hmul2(o2, tanh2(__floats2half2_rn(c1_reg[0], c1_reg[1])));
            ((unsigned short*)hB1)[(hrow + 2 * bC) * 2 + (hC & 1)] =
                __half_as_ushort(__low2half(h2v));
            ((unsigned short*)hB1)[(hrow + 2 * (bC + 1)) * 2 + (hC & 1)] =
                __half_as_ushort(__high2half(h2v));
        }
        // ---- activation L2 (f16x2): h2[t-1] (skip at t=0)
        if (t >= 1) {
            __half2 G[4];
            #pragma unroll
            for (int p = 0; p < 4; ++p) {
                uint32_t u = sG2[(hC + 64 * p) * GS2 + gcol];
                G[p] = *(__half2*)&u;
            }
            __half2 t2;
            t2 = tanh2(__hmul2(__hadd2(G[0], bv1h[0]), h05));
            __half2 i2 = __hfma2(t2, h05, h05);
            t2 = tanh2(__hmul2(__hadd2(G[1], bv1h[1]), h05));
            __half2 f2 = __hfma2(t2, h05, h05);
            __half2 g2 = tanh2(__hadd2(G[2], bv1h[2]));
            t2 = tanh2(__hmul2(__hadd2(G[3], bv1h[3]), h05));
            __half2 o2 = __hfma2(t2, h05, h05);
            float2 fi = __half22float2(i2);
            float2 ff = __half22float2(f2);
            float2 fg = __half22float2(g2);
            c2_reg[0] = ff.x * c2_reg[0] + fi.x * fg.x;
            c2_reg[1] = ff.y * c2_reg[1] + fi.y * fg.y;
            __half2 h2v = __hmul2(o2, tanh2(__floats2half2_rn(c2_reg[0], c2_reg[1])));
            ((unsigned short*)hB2)[(hrow + 2 * bC) * 2 + (hC & 1)] =
                __half_as_ushort(__low2half(h2v));
            ((unsigned short*)hB2)[(hrow + 2 * (bC + 1)) * 2 + (hC & 1)] =
                __half_as_ushort(__high2half(h2v));
        }
        __syncthreads();   // BAR2: h/x writes visible for next step
    }

    // epilogue: gates2[T-1] from h1[T-1] and h2[T-2] -> h2[T-1]
    {
        float acc2[2][4] = {};
        #pragma unroll
        for (int kk = 0; kk < 4; ++kk) {
            #pragma unroll
            for (int nt = 0; nt < 2; ++nt) {
                uint2 b1v = *(const uint2*)(hB1 + bb + kk * 4 * HS + nt * 16);
                uint2 b2v = *(const uint2*)(hB2 + bb + kk * 4 * HS + nt * 16);
                mma16816(acc2[nt], c[kk], b1v.x, b1v.y);
                mma16816(acc2[nt], d[kk], b2v.x, b2v.y);
            }
        }
        #pragma unroll
        for (int nt = 0; nt < 2; ++nt) {
            const int col = 4 * nt + tg;
            sG2[(16 * w + g) * GS2 + col]     = packf(acc2[nt][0], acc2[nt][1]);
            sG2[(16 * w + g + 8) * GS2 + col] = packf(acc2[nt][2], acc2[nt][3]);
        }
        __syncthreads();

        #pragma unroll
        for (int q = 0; q < 2; ++q) {
            float G[4];
            #pragma unroll
            for (int p = 0; p < 4; ++p) {
                uint32_t u = sG2[(hC + 64 * p) * GS2 + gcol];
                __half2 hv = *(__half2*)&u;
                G[p] = q ? __half2float(__high2half(hv))
                         : __half2float(__low2half(hv));
            }
            float gi = fsig(G[0] + bv1f[0]);
            float gf = fsig(G[1] + bv1f[1]);
            float gg = ftanh(G[2] + bv1f[2]);
            float go = fsig(G[3] + bv1f[3]);
            const float cc = gf * c2_reg[q] + gi * gg;
            sHL[hC * 20 + bC + q] = go * ftanh(cc);
        }
        __syncthreads();
    }

    // FC head: out = h2_last @ fc_w^T + fc_b
    for (int idx = tid; idx < 16 * O; idx += 512) {
        int b = idx / O, o = idx - (idx / O) * O;
        float sum = fc_b[o];
        #pragma unroll
        for (int hh = 0; hh < H; ++hh)
            sum += sHL[hh * 20 + b] * fc_w[o * H + hh];
        out[(batch0 + b) * O + o] = sum;
    }
}

extern "C" void kernel_launch(void* const* d_in, const int* in_sizes, int n_in,
                              void* d_out, int out_size) {
    const float* x     = (const float*)d_in[0];
    const float* w_ih0 = (const float*)d_in[1];
    const float* w_hh0 = (const float*)d_in[2];
    const float* b_ih0 = (const float*)d_in[3];
    const float* b_hh0 = (const float*)d_in[4];
    const float* w_ih1 = (const float*)d_in[5];
    const float* w_hh1 = (const float*)d_in[6];
    const float* b_ih1 = (const float*)d_in[7];
    const float* b_hh1 = (const float*)d_in[8];
    const float* fc_w  = (const float*)d_in[9];
    const float* fc_b  = (const float*)d_in[10];
    float* out = (float*)d_out;

    // smem words: 2*640(hB) + 2*960(xB) + 12*1024(sWI) + 2*256*GS2 + 320(sHL)
    const int smR = (2 * HWORDS + 2 * XWORDS + 12 * 1024
                     + 2 * 256 * GS2 + 64 * 20) * 4 + 256;

    cudaFuncSetAttribute(lstm_fused,
                         cudaFuncAttributeMaxDynamicSharedMemorySize, smR);

    lstm_fused<<<B / 16, 512, smR>>>(
        x, w_ih0, w_hh0, b_ih0, b_hh0,
        w_ih1, w_hh1, b_ih1, b_hh1, fc_w, fc_b, out);
}